// round 1
// baseline (speedup 1.0000x reference)
#include <cuda_runtime.h>
#include <math.h>

#define BB 8
#define CC 64
#define NN 4096
#define TOT (BB*CC*NN)

// Scratch (allocation-free: __device__ globals)
__device__ float g_z[TOT];          // z = W @ x, 8MB
__device__ float g_sum[BB*CC];      // Σ_n z per (b,o)
__device__ float g_sumsq[BB*CC];    // Σ_n z² per (b,o)
__device__ float g_s[BB];           // s_b
__device__ float g_scale[BB*CC];
__device__ float g_bias[BB*CC];

// K0: s_b = Σ_n relu(tanh(w))², plus zero the accumulators
__global__ void k0_prep(const float* __restrict__ w) {
    int b = blockIdx.x;
    int t = threadIdx.x;            // 256
    if (t < CC) { g_sum[b*CC + t] = 0.f; g_sumsq[b*CC + t] = 0.f; }
    float acc = 0.f;
    for (int i = t; i < NN; i += 256) {
        float v = tanhf(w[b*NN + i]);
        v = fmaxf(v, 0.f);
        acc = fmaf(v, v, acc);
    }
    __shared__ float red[256];
    red[t] = acc; __syncthreads();
    for (int s = 128; s > 0; s >>= 1) {
        if (t < s) red[t] += red[t + s];
        __syncthreads();
    }
    if (t == 0) g_s[b] = red[0];
}

// K1: z[b,o,n] = Σ_c W[o,c] x[b,c,n]; accumulate Σz, Σz² per (b,o).
// Block: one (b, 64-wide n-tile). 256 threads, 4o x 4n microtiles.
__global__ __launch_bounds__(256) void k1_gemm(const float* __restrict__ x,
                                               const float* __restrict__ W) {
    __shared__ float xs[64][64];    // xs[c][j]
    __shared__ float wt[64][68];    // wt[c][o], padded for conflicts + f4 alignment
    int b  = blockIdx.y;
    int n0 = blockIdx.x * 64;
    int t  = threadIdx.x;

    // Load W transposed: wt[c][o] = W[o*64+c]
    #pragma unroll
    for (int i = 0; i < 4096; i += 256) {
        int idx = i + t;
        int o = idx >> 6, c = idx & 63;
        wt[c][o] = W[idx];
    }
    // Load x tile (float4, coalesced): x[b][c][n0+j]
    const float4* x4 = (const float4*)(x + ((size_t)b * CC) * NN + n0);
    #pragma unroll
    for (int i = 0; i < 1024; i += 256) {
        int idx = i + t;                 // 64 c-rows * 16 float4
        int c = idx >> 4, j4 = idx & 15;
        float4 v = x4[c * (NN/4) + j4];
        *((float4*)&xs[c][j4 * 4]) = v;
    }
    __syncthreads();

    int tx = t & 15, ty = t >> 4;        // tx: n-group, ty: o-group
    float acc[4][4];
    #pragma unroll
    for (int i = 0; i < 4; i++)
        #pragma unroll
        for (int j = 0; j < 4; j++) acc[i][j] = 0.f;

    #pragma unroll
    for (int c = 0; c < 64; c++) {
        float4 a  = *((const float4*)&wt[c][ty * 4]);
        float4 xv = *((const float4*)&xs[c][tx * 4]);
        float av[4] = {a.x, a.y, a.z, a.w};
        float xvv[4] = {xv.x, xv.y, xv.z, xv.w};
        #pragma unroll
        for (int i = 0; i < 4; i++)
            #pragma unroll
            for (int j = 0; j < 4; j++)
                acc[i][j] = fmaf(av[i], xvv[j], acc[i][j]);
    }

    // Local stats over the 4 n's of each o row
    float lsum[4], lsq[4];
    #pragma unroll
    for (int i = 0; i < 4; i++) {
        lsum[i] = acc[i][0] + acc[i][1] + acc[i][2] + acc[i][3];
        lsq[i]  = acc[i][0]*acc[i][0] + acc[i][1]*acc[i][1]
                + acc[i][2]*acc[i][2] + acc[i][3]*acc[i][3];
    }
    // Reduce across the 16 tx lanes (xor widths < 16 stay in-group)
    #pragma unroll
    for (int off = 8; off > 0; off >>= 1) {
        #pragma unroll
        for (int i = 0; i < 4; i++) {
            lsum[i] += __shfl_xor_sync(0xFFFFFFFFu, lsum[i], off);
            lsq[i]  += __shfl_xor_sync(0xFFFFFFFFu, lsq[i],  off);
        }
    }
    if (tx == 0) {
        #pragma unroll
        for (int i = 0; i < 4; i++) {
            int o = ty * 4 + i;
            atomicAdd(&g_sum[b*CC + o],   lsum[i]);
            atomicAdd(&g_sumsq[b*CC + o], lsq[i]);
        }
    }
    // Write z
    float* zp = g_z + ((size_t)b * CC) * NN + n0;
    #pragma unroll
    for (int i = 0; i < 4; i++) {
        int o = ty * 4 + i;
        float4 v = make_float4(acc[i][0], acc[i][1], acc[i][2], acc[i][3]);
        ((float4*)(zp + (size_t)o * NN))[tx] = v;
    }
}

// K2: analytic BN stats -> per-(b,o) scale/bias. 1 block, 64 threads (o).
__global__ void k2_finalize(const float* __restrict__ conv_b,
                            const float* __restrict__ gamma,
                            const float* __restrict__ beta) {
    int o = threadIdx.x;
    float alpha[BB], offv[BB];
    float mean_acc = 0.f, sq_acc = 0.f;
    #pragma unroll
    for (int b = 0; b < BB; b++) {
        float s = g_s[b];
        float a = 1.f / (1.f + (float)NN * s);
        float Z = g_sum[b*CC + o];
        float Q = g_sumsq[b*CC + o];
        float off = a * s * Z + conv_b[o];
        alpha[b] = a; offv[b] = off;
        mean_acc += a * Z + (float)NN * off;
        sq_acc   += a*a*Q + 2.f*a*off*Z + (float)NN * off * off;
    }
    const float inv_cnt = 1.f / (float)(BB * NN);
    float mean = mean_acc * inv_cnt;
    float var  = sq_acc * inv_cnt - mean * mean;
    float invstd = rsqrtf(var + 1e-5f);
    float g = gamma[o] * invstd;
    float be = beta[o];
    #pragma unroll
    for (int b = 0; b < BB; b++) {
        g_scale[b*CC + o] = alpha[b] * g;
        g_bias[b*CC + o]  = (offv[b] - mean) * g + be;
    }
}

// K3: out = relu(scale * z + bias), vectorized float4
__global__ __launch_bounds__(256) void k3_epilogue(float* __restrict__ out) {
    int idx = blockIdx.x * blockDim.x + threadIdx.x;   // float4 index, 524288 total
    int bc = idx >> 10;                                // 1024 float4 per (b,o) row
    float sc = g_scale[bc], bi = g_bias[bc];
    float4 z = ((const float4*)g_z)[idx];
    float4 r;
    r.x = fmaxf(fmaf(sc, z.x, bi), 0.f);
    r.y = fmaxf(fmaf(sc, z.y, bi), 0.f);
    r.z = fmaxf(fmaf(sc, z.z, bi), 0.f);
    r.w = fmaxf(fmaf(sc, z.w, bi), 0.f);
    ((float4*)out)[idx] = r;
}

extern "C" void kernel_launch(void* const* d_in, const int* in_sizes, int n_in,
                              void* d_out, int out_size) {
    const float* x      = (const float*)d_in[0];  // [8,64,4096,1]
    const float* w      = (const float*)d_in[1];  // [8,4096]
    const float* conv_w = (const float*)d_in[2];  // [64,64,1,1]
    const float* conv_b = (const float*)d_in[3];  // [64]
    const float* gamma  = (const float*)d_in[4];  // [64]
    const float* beta   = (const float*)d_in[5];  // [64]
    float* out = (float*)d_out;

    k0_prep<<<BB, 256>>>(w);
    k1_gemm<<<dim3(NN/64, BB), 256>>>(x, conv_w);
    k2_finalize<<<1, 64>>>(conv_b, gamma, beta);
    k3_epilogue<<<(TOT/4 + 255)/256, 256>>>(out);
}

// round 3
// speedup vs baseline: 1.1958x; 1.1958x over previous
#include <cuda_runtime.h>
#include <math.h>

#define BB 8
#define CC 64
#define NN 4096
#define TOT (BB*CC*NN)
#define NBLK 32            // n-tiles per batch in K1 (4096/128)

// Scratch (allocation-free: __device__ globals)
__device__ float g_z[TOT];                  // z = W @ x  (8 MB)
__device__ float g_psum[BB*NBLK*CC];        // per-block partial Σz
__device__ float g_psq [BB*NBLK*CC];        // per-block partial Σz²
__device__ float g_scale[BB*CC];
__device__ float g_bias [BB*CC];

// ---- f32x2 packed helpers (sm_103a) ----
__device__ __forceinline__ unsigned long long ffma2(unsigned long long a,
                                                    unsigned long long b,
                                                    unsigned long long c) {
    unsigned long long d;
    asm("fma.rn.f32x2 %0, %1, %2, %3;" : "=l"(d) : "l"(a), "l"(b), "l"(c));
    return d;
}
__device__ __forceinline__ unsigned long long packdup(float v) {
    unsigned long long r;
    asm("mov.b64 %0, {%1, %2};" : "=l"(r) : "f"(v), "f"(v));
    return r;
}
__device__ __forceinline__ void unpack2(unsigned long long v, float& lo, float& hi) {
    asm("mov.b64 {%0, %1}, %2;" : "=f"(lo), "=f"(hi) : "l"(v));
}

// ============================================================================
// K1: z[b,o,n] = Σ_c W[o,c]·x[b,c,n], 64o × 128n tile per block, f32x2 FMAs.
// Also writes per-block partial Σz, Σz² (no atomics, no pre-zeroing needed).
// ============================================================================
__global__ __launch_bounds__(256) void k1_gemm(const float* __restrict__ x,
                                               const float* __restrict__ W) {
    __shared__ float xs[64][128];       // xs[c][j], row stride 512B (16B-aligned)
    __shared__ float wt[64][68];        // wt[c][o], stride 272B (16B-aligned)
    const int b  = blockIdx.y;
    const int nb = blockIdx.x;
    const int n0 = nb * 128;
    const int t  = threadIdx.x;

    // Load W transposed: wt[c][o] = W[o*64 + c]
    #pragma unroll
    for (int i = 0; i < 4096; i += 256) {
        int idx = i + t;
        wt[idx & 63][idx >> 6] = W[idx];
    }
    // Load x tile (float4, coalesced)
    const float4* x4 = (const float4*)(x + ((size_t)b * CC) * NN + n0);
    #pragma unroll
    for (int i = 0; i < 2048; i += 256) {
        int idx = i + t;                 // 64 c-rows * 32 float4
        int c = idx >> 5, j = idx & 31;
        ((float4*)xs[c])[j] = x4[c * (NN / 4) + j];
    }
    __syncthreads();

    const int tx = t & 15, ty = t >> 4;  // tx: n-group, ty: o-group
    // Each thread: 4 o's (ty*4..+3) × 8 n's  = chunk A (tx*4..+3) and
    // chunk B (64+tx*4..+3), each chunk as 2 f32x2 pairs.
    unsigned long long acc[4][4] = {};   // bit pattern 0 == (0.f, 0.f)

    #pragma unroll
    for (int c = 0; c < 64; c++) {
        float4 wv = *(const float4*)&wt[c][ty * 4];
        ulonglong2 xa = *(const ulonglong2*)&xs[c][tx * 4];
        ulonglong2 xb = *(const ulonglong2*)&xs[c][64 + tx * 4];
        unsigned long long wd0 = packdup(wv.x);
        unsigned long long wd1 = packdup(wv.y);
        unsigned long long wd2 = packdup(wv.z);
        unsigned long long wd3 = packdup(wv.w);
        acc[0][0] = ffma2(wd0, xa.x, acc[0][0]);
        acc[0][1] = ffma2(wd0, xa.y, acc[0][1]);
        acc[0][2] = ffma2(wd0, xb.x, acc[0][2]);
        acc[0][3] = ffma2(wd0, xb.y, acc[0][3]);
        acc[1][0] = ffma2(wd1, xa.x, acc[1][0]);
        acc[1][1] = ffma2(wd1, xa.y, acc[1][1]);
        acc[1][2] = ffma2(wd1, xb.x, acc[1][2]);
        acc[1][3] = ffma2(wd1, xb.y, acc[1][3]);
        acc[2][0] = ffma2(wd2, xa.x, acc[2][0]);
        acc[2][1] = ffma2(wd2, xa.y, acc[2][1]);
        acc[2][2] = ffma2(wd2, xb.x, acc[2][2]);
        acc[2][3] = ffma2(wd2, xb.y, acc[2][3]);
        acc[3][0] = ffma2(wd3, xa.x, acc[3][0]);
        acc[3][1] = ffma2(wd3, xa.y, acc[3][1]);
        acc[3][2] = ffma2(wd3, xb.x, acc[3][2]);
        acc[3][3] = ffma2(wd3, xb.y, acc[3][3]);
    }

    // Unpack to scalar values v[o][n8]
    float v[4][8];
    #pragma unroll
    for (int i = 0; i < 4; i++) {
        unpack2(acc[i][0], v[i][0], v[i][1]);
        unpack2(acc[i][1], v[i][2], v[i][3]);
        unpack2(acc[i][2], v[i][4], v[i][5]);
        unpack2(acc[i][3], v[i][6], v[i][7]);
    }

    // Per-thread stats, then reduce across the 16 tx lanes (stay in half-warp)
    float lsum[4], lsq[4];
    #pragma unroll
    for (int i = 0; i < 4; i++) {
        float s = 0.f, q = 0.f;
        #pragma unroll
        for (int j = 0; j < 8; j++) { s += v[i][j]; q = fmaf(v[i][j], v[i][j], q); }
        lsum[i] = s; lsq[i] = q;
    }
    #pragma unroll
    for (int off = 8; off > 0; off >>= 1) {
        #pragma unroll
        for (int i = 0; i < 4; i++) {
            lsum[i] += __shfl_xor_sync(0xFFFFFFFFu, lsum[i], off);
            lsq[i]  += __shfl_xor_sync(0xFFFFFFFFu, lsq[i],  off);
        }
    }
    if (tx == 0) {
        int base = (b * NBLK + nb) * CC + ty * 4;
        #pragma unroll
        for (int i = 0; i < 4; i++) {
            g_psum[base + i] = lsum[i];
            g_psq [base + i] = lsq[i];
        }
    }

    // Write z (coalesced: 16 lanes × contiguous float4 per chunk)
    float* zp = g_z + ((size_t)b * CC) * NN + n0;
    #pragma unroll
    for (int i = 0; i < 4; i++) {
        int o = ty * 4 + i;
        *(float4*)(zp + (size_t)o * NN + tx * 4) =
            make_float4(v[i][0], v[i][1], v[i][2], v[i][3]);
        *(float4*)(zp + (size_t)o * NN + 64 + tx * 4) =
            make_float4(v[i][4], v[i][5], v[i][6], v[i][7]);
    }
}

// ============================================================================
// K2: s_b from w, reduce partials, closed-form BN -> scale/bias. One block.
// ============================================================================
__global__ __launch_bounds__(512) void k2_finalize(const float* __restrict__ w,
                                                   const float* __restrict__ conv_b,
                                                   const float* __restrict__ gamma,
                                                   const float* __restrict__ beta) {
    __shared__ float s_s[BB];
    __shared__ float sZ[BB][CC];
    __shared__ float sQ[BB][CC];
    __shared__ float part[16];
    const int t = threadIdx.x;

    // Phase 1: s_b = Σ_n relu(tanh(w))². 64 threads per batch.
    {
        int b = t >> 6, l = t & 63;
        float acc = 0.f;
        for (int i = l; i < NN; i += 64) {
            float vv = tanhf(w[b * NN + i]);
            vv = fmaxf(vv, 0.f);
            acc = fmaf(vv, vv, acc);
        }
        #pragma unroll
        for (int off = 16; off > 0; off >>= 1)
            acc += __shfl_xor_sync(0xFFFFFFFFu, acc, off);
        if ((t & 31) == 0) part[t >> 5] = acc;
    }
    __syncthreads();
    if (t < BB) s_s[t] = part[2 * t] + part[2 * t + 1];

    // Phase 2a: reduce K1 partials. Thread t ↔ (b,o).
    {
        int b = t >> 6, o = t & 63;
        float Z = 0.f, Q = 0.f;
        #pragma unroll
        for (int nb = 0; nb < NBLK; nb++) {
            Z += g_psum[(b * NBLK + nb) * CC + o];
            Q += g_psq [(b * NBLK + nb) * CC + o];
        }
        sZ[b][o] = Z; sQ[b][o] = Q;
    }
    __syncthreads();

    // Phase 2b: closed-form BN stats per channel o.
    if (t < CC) {
        int o = t;
        float cb = conv_b[o];
        float alpha[BB], offv[BB];
        float mean_acc = 0.f, sq_acc = 0.f;
        #pragma unroll
        for (int b = 0; b < BB; b++) {
            float s = s_s[b];
            float a = 1.f / (1.f + (float)NN * s);
            float Z = sZ[b][o];
            float Q = sQ[b][o];
            float off = a * s * Z + cb;
            alpha[b] = a; offv[b] = off;
            mean_acc += a * Z + (float)NN * off;
            sq_acc   += a * a * Q + 2.f * a * off * Z + (float)NN * off * off;
        }
        const float inv_cnt = 1.f / (float)(BB * NN);
        float mean = mean_acc * inv_cnt;
        float var  = sq_acc * inv_cnt - mean * mean;
        float invstd = rsqrtf(var + 1e-5f);
        float g  = gamma[o] * invstd;
        float be = beta[o];
        #pragma unroll
        for (int b = 0; b < BB; b++) {
            g_scale[b * CC + o] = alpha[b] * g;
            g_bias [b * CC + o] = (offv[b] - mean) * g + be;
        }
    }
}

// ============================================================================
// K3: out = relu(scale*z + bias). One block per (b,c) row; 4 indep float4/thread.
// ============================================================================
__global__ __launch_bounds__(256) void k3_epilogue(float* __restrict__ out) {
    const int row = blockIdx.x;                 // 512 rows of 4096 floats
    const float sc = g_scale[row];
    const float bi = g_bias[row];
    const float4* z = (const float4*)(g_z + (size_t)row * NN);
    float4* op = (float4*)(out + (size_t)row * NN);
    const int t = threadIdx.x;

    float4 v[4];
    #pragma unroll
    for (int i = 0; i < 4; i++) v[i] = z[t + i * 256];
    #pragma unroll
    for (int i = 0; i < 4; i++) {
        float4 r;
        r.x = fmaxf(fmaf(sc, v[i].x, bi), 0.f);
        r.y = fmaxf(fmaf(sc, v[i].y, bi), 0.f);
        r.z = fmaxf(fmaf(sc, v[i].z, bi), 0.f);
        r.w = fmaxf(fmaf(sc, v[i].w, bi), 0.f);
        op[t + i * 256] = r;
    }
}

extern "C" void kernel_launch(void* const* d_in, const int* in_sizes, int n_in,
                              void* d_out, int out_size) {
    const float* x      = (const float*)d_in[0];  // [8,64,4096,1]
    const float* w      = (const float*)d_in[1];  // [8,4096]
    const float* conv_w = (const float*)d_in[2];  // [64,64,1,1]
    const float* conv_b = (const float*)d_in[3];  // [64]
    const float* gamma  = (const float*)d_in[4];  // [64]
    const float* beta   = (const float*)d_in[5];  // [64]
    float* out = (float*)d_out;

    k1_gemm<<<dim3(NBLK, BB), 256>>>(x, conv_w);
    k2_finalize<<<1, 512>>>(w, conv_b, gamma, beta);
    k3_epilogue<<<BB * CC, 256>>>(out);
}